// round 12
// baseline (speedup 1.0000x reference)
#include <cuda_runtime.h>
#include <math.h>
#include <stdint.h>

// ---------------------------------------------------------------------------
// Shapes (fixed for this problem)
//   x:    (64, 1, 112, 112)
//   s1: conv 1->32 s1  @112 ; BNstats ; deform(32) @112
//   s2: conv 32->64 s2 @112->56 ; BNstats ; deform(64) @56
//   s3: conv 64->128 s1 @56 ; BNstats ; deform(128) @56
//   s4: conv 128->128 s2 @56->28 ; BNstats ; pool(+BN)+fc+softmax -> (64,10)
// BN apply is never materialized:
//   - offset convs apply BN per-element during smem staging (padding stays 0,
//     matching the reference's zero padding in BN space)
//   - deform applies BN on the interpolated value (affine commutes w/ bilinear)
//   - final BN folds into the head after pooling (mean commutes w/ affine)
// ---------------------------------------------------------------------------

#define B_ 64

// ---- scratch buffer (single __device__ global; offsets in floats) ----------
constexpr size_t SZ_A1   = (size_t)B_ * 32 * 112 * 112;
constexpr size_t SZ_OFF1 = (size_t)B_ * 64 * 112 * 112;
constexpr size_t SZ_D1   = SZ_A1;
constexpr size_t SZ_A2   = (size_t)B_ * 64 * 56 * 56;
constexpr size_t SZ_OFF2 = (size_t)B_ * 128 * 56 * 56;
constexpr size_t SZ_D2   = SZ_A2;
constexpr size_t SZ_A3   = (size_t)B_ * 128 * 56 * 56;
constexpr size_t SZ_OFF3 = (size_t)B_ * 256 * 56 * 56;
constexpr size_t SZ_D3   = SZ_A3;
constexpr size_t SZ_A4   = (size_t)B_ * 128 * 28 * 28;
constexpr size_t SZ_PART = (size_t)128 * 64;
constexpr size_t SZ_SS   = 128;

constexpr size_t OFF_A1   = 0;
constexpr size_t OFF_OFF1 = OFF_A1   + SZ_A1;
constexpr size_t OFF_D1   = OFF_OFF1 + SZ_OFF1;
constexpr size_t OFF_A2   = OFF_D1   + SZ_D1;
constexpr size_t OFF_OFF2 = OFF_A2   + SZ_A2;
constexpr size_t OFF_D2   = OFF_OFF2 + SZ_OFF2;
constexpr size_t OFF_A3   = OFF_D2   + SZ_D2;
constexpr size_t OFF_OFF3 = OFF_A3   + SZ_A3;
constexpr size_t OFF_D3   = OFF_OFF3 + SZ_OFF3;
constexpr size_t OFF_A4   = OFF_D3   + SZ_D3;
constexpr size_t OFF_PSUM = OFF_A4   + SZ_A4;
constexpr size_t OFF_PSQ  = OFF_PSUM + SZ_PART;
constexpr size_t OFF_SC1  = OFF_PSQ  + SZ_PART;   // per-stage scale/shift
constexpr size_t OFF_SH1  = OFF_SC1  + SZ_SS;
constexpr size_t OFF_SC2  = OFF_SH1  + SZ_SS;
constexpr size_t OFF_SH2  = OFF_SC2  + SZ_SS;
constexpr size_t OFF_SC3  = OFF_SH2  + SZ_SS;
constexpr size_t OFF_SH3  = OFF_SC3  + SZ_SS;
constexpr size_t OFF_SC4  = OFF_SH3  + SZ_SS;
constexpr size_t OFF_SH4  = OFF_SC4  + SZ_SS;
constexpr size_t TOTAL_F  = OFF_SH4  + SZ_SS;

__device__ float g_buf[TOTAL_F];

// ---- packed fp32x2 helpers (Blackwell FFMA2 path; bit-exact fp32) ----------
typedef unsigned long long u64t;

__device__ __forceinline__ u64t pack2(float lo, float hi) {
    u64t d;
    asm("mov.b64 %0, {%1, %2};" : "=l"(d) : "f"(lo), "f"(hi));
    return d;
}
__device__ __forceinline__ void unpack2(u64t v, float& lo, float& hi) {
    asm("mov.b64 {%0, %1}, %2;" : "=f"(lo), "=f"(hi) : "l"(v));
}
__device__ __forceinline__ u64t fma2(u64t a, u64t b, u64t c) {
    u64t d;
    asm("fma.rn.f32x2 %0, %1, %2, %3;" : "=l"(d) : "l"(a), "l"(b), "l"(c));
    return d;
}

// ---------------------------------------------------------------------------
// Direct 3x3 conv, pad=1, FFMA2 + software-pipelined staging.
// Block: 256 threads, output tile 32(x) x TOY(y) pixels x 32 co.
// Thread: PX adjacent pixels x 8 co (4 co-pairs) -> 4*PX f32x2 accumulators.
// stride1: PX=8, TOY=16 ; stride2: PX=4, TOY=8.
// Optional per-channel affine (bnsc/bnsh) applied to in-bounds elements during
// smem staging — implements "conv(BN(x))" with correct zero padding.
// ---------------------------------------------------------------------------
template <int STRIDE, int PX, int TOY>
__global__ __launch_bounds__(256)
void conv3x3_f2_kernel(const float* __restrict__ in, const float* __restrict__ wgt,
                       const float* __restrict__ bias,
                       const float* __restrict__ bnsc, const float* __restrict__ bnsh,
                       float* __restrict__ out,
                       int Cin, int Cout, int Hin, int Win, int Hout, int Wout,
                       int tilesX, int doRelu)
{
    constexpr int TOX = 32, KO = 32, CH = 32;
    constexpr int TXG = TOX / PX;                 // 4 (PX=8) / 8 (PX=4)
    constexpr int IW  = (TOX - 1) * STRIDE + 3;
    constexpr int IWP = IW + 1;
    constexpr int IH  = (TOY - 1) * STRIDE + 3;
    constexpr int NPIX  = IH * IWP;
    constexpr int NSLOT = (NPIX + 255) / 256;
    constexpr int NC  = (PX - 1) * STRIDE + 3;    // 10 (s1) / 9 (s2)

    __shared__ float s_in[2][NPIX];
    __shared__ float s_w[CH * 9 * KO];            // 36 KB

    const int b    = blockIdx.z;
    const int co0  = blockIdx.y * KO;
    const int tile = blockIdx.x;
    const int oy0  = (tile / tilesX) * TOY;
    const int ox0  = (tile % tilesX) * TOX;
    const int tid  = threadIdx.x;
    const int cog  = tid >> 6;                    // 0..3 -> 8 co's
    const int rem  = tid & 63;
    const int ty   = rem / TXG;                   // 0..TOY-1
    const int txg  = rem % TXG;                   // pixel col group of PX

    const int iy0 = oy0 * STRIDE - 1;
    const int ix0 = ox0 * STRIDE - 1;
    const int rbase = ty * STRIDE;
    const int cbase = txg * PX * STRIDE;
    const int HinWin = Hin * Win;

    // ---- per-thread staging slots: offsets + validity are ci-invariant ----
    int  soff[NSLOT];
    bool sval[NSLOT];
    bool sput[NSLOT];
    #pragma unroll
    for (int s = 0; s < NSLOT; ++s) {
        int idx = tid + s * 256;
        int r = idx / IWP, c = idx - r * IWP;
        int iy = iy0 + r, ix = ix0 + c;
        sput[s] = (idx < NPIX);
        sval[s] = sput[s] && (c < IW) && iy >= 0 && iy < Hin && ix >= 0 && ix < Win;
        soff[s] = iy * Win + ix;
    }

    const float* inB = in + (size_t)b * Cin * HinWin;
    float rg[NSLOT];

    auto prefetch = [&](int ci) {
        const float* inC = inB + (size_t)ci * HinWin;
        #pragma unroll
        for (int s = 0; s < NSLOT; ++s)
            rg[s] = sval[s] ? __ldg(inC + soff[s]) : 0.f;
    };
    // stage channel `ci`'s prefetched data; apply BN affine to in-bounds
    // elements (padding must remain 0 in BN space, matching the reference)
    auto put = [&](int ci, int bufi) {
        if (bnsc) {
            float sc = bnsc[ci], sh = bnsh[ci];
            #pragma unroll
            for (int s = 0; s < NSLOT; ++s)
                if (sput[s]) s_in[bufi][tid + s * 256] = sval[s] ? fmaf(rg[s], sc, sh) : 0.f;
        } else {
            #pragma unroll
            for (int s = 0; s < NSLOT; ++s)
                if (sput[s]) s_in[bufi][tid + s * 256] = rg[s];
        }
    };
    auto stage_w = [&](int cb) {
        const int ce  = (cb + CH < Cin) ? cb + CH : Cin;
        const int cnt = ce - cb;
        for (int i = tid; i < cnt * 9 * KO; i += 256) {
            int col = i & (KO - 1);
            int t   = i >> 5;            // KO = 32
            int k   = t % 9;
            int cl  = t / 9;
            s_w[i] = wgt[((size_t)(co0 + col) * Cin + (cb + cl)) * 9 + k];
        }
    };

    u64t acc[4][PX];
    #pragma unroll
    for (int mp = 0; mp < 4; ++mp)
        #pragma unroll
        for (int p = 0; p < PX; ++p) acc[mp][p] = 0ull;

    // ---- prologue ----
    prefetch(0);
    put(0, 0);
    if (Cin > 1) prefetch(1);
    stage_w(0);
    __syncthreads();

    // ---- main loop: 1 barrier / cin (2 at chunk boundaries) ----
    for (int ci = 0; ci < Cin; ++ci) {
        if (ci + 1 < Cin) put(ci + 1, (ci + 1) & 1);
        if (ci + 2 < Cin) prefetch(ci + 2);

        {
            const int cl = ci & (CH - 1);
            const float* xp = s_in[ci & 1] + rbase * IWP + cbase;
            const float* wb = s_w + (cl * 9) * KO + cog * 8;
            #pragma unroll
            for (int kr = 0; kr < 3; ++kr) {
                u64t xs[NC];
                #pragma unroll
                for (int c = 0; c < NC; ++c) {
                    float v = xp[kr * IWP + c];
                    xs[c] = pack2(v, v);
                }
                #pragma unroll
                for (int kc = 0; kc < 3; ++kc) {
                    const float* wk = wb + (kr * 3 + kc) * KO;
                    u64t w0 = *(const u64t*)(wk + 0);
                    u64t w1 = *(const u64t*)(wk + 2);
                    u64t w2 = *(const u64t*)(wk + 4);
                    u64t w3 = *(const u64t*)(wk + 6);
                    #pragma unroll
                    for (int p = 0; p < PX; ++p) {
                        u64t x = xs[p * STRIDE + kc];
                        acc[0][p] = fma2(w0, x, acc[0][p]);
                        acc[1][p] = fma2(w1, x, acc[1][p]);
                        acc[2][p] = fma2(w2, x, acc[2][p]);
                        acc[3][p] = fma2(w3, x, acc[3][p]);
                    }
                }
            }
        }

        if ((ci + 1) < Cin && ((ci + 1) & (CH - 1)) == 0) {
            __syncthreads();
            stage_w(ci + 1);
        }
        __syncthreads();
    }

    // ---- epilogue ----
    const int oy = oy0 + ty;
    if (oy < Hout) {
        #pragma unroll
        for (int mp = 0; mp < 4; ++mp) {
            int coL = co0 + cog * 8 + mp * 2;
            float bL = bias ? bias[coL] : 0.f;
            float bH = bias ? bias[coL + 1] : 0.f;
            float* oL = out + ((size_t)b * Cout + coL) * (size_t)Hout * Wout + (size_t)oy * Wout;
            float* oH = oL + (size_t)Hout * Wout;
            #pragma unroll
            for (int p = 0; p < PX; ++p) {
                int ox = ox0 + txg * PX + p;
                if (ox < Wout) {
                    float lo, hi;
                    unpack2(acc[mp][p], lo, hi);
                    lo += bL; hi += bH;
                    if (doRelu) { lo = fmaxf(lo, 0.f); hi = fmaxf(hi, 0.f); }
                    oL[ox] = lo;
                    oH[ox] = hi;
                }
            }
        }
    }
}

// ---------------------------------------------------------------------------
// BN stats: deterministic two-stage reduction over (N, H, W) per channel.
// ---------------------------------------------------------------------------
__global__ __launch_bounds__(256)
void bn_partial_kernel(const float* __restrict__ x, float* __restrict__ psum,
                       float* __restrict__ psq, int C, int HW, int S)
{
    const int c = blockIdx.x;
    const int s = blockIdx.y;
    const long n = (long)B_ * HW;
    const long chunk = (n + S - 1) / S;
    const long lo = (long)s * chunk;
    const long hi = (lo + chunk < n) ? lo + chunk : n;

    float sum = 0.f, sq = 0.f;
    for (long i = lo + threadIdx.x; i < hi; i += 256) {
        long b = i / HW;
        int  p = (int)(i - b * HW);
        float v = x[(b * C + c) * (long)HW + p];
        sum += v;
        sq  += v * v;
    }
    __shared__ float ss[256], sQ[256];
    ss[threadIdx.x] = sum;
    sQ[threadIdx.x] = sq;
    __syncthreads();
    for (int step = 128; step > 0; step >>= 1) {
        if (threadIdx.x < step) {
            ss[threadIdx.x] += ss[threadIdx.x + step];
            sQ[threadIdx.x] += sQ[threadIdx.x + step];
        }
        __syncthreads();
    }
    if (threadIdx.x == 0) {
        psum[c * S + s] = ss[0];
        psq [c * S + s] = sQ[0];
    }
}

__global__ void bn_finalize_kernel(const float* __restrict__ psum, const float* __restrict__ psq,
                                   const float* __restrict__ g, const float* __restrict__ be,
                                   float* __restrict__ scale, float* __restrict__ shift,
                                   int S, float invN)
{
    const int c = blockIdx.x;
    __shared__ float ss[64], sQ[64];
    float a = 0.f, q = 0.f;
    if (threadIdx.x < S) { a = psum[c * S + threadIdx.x]; q = psq[c * S + threadIdx.x]; }
    ss[threadIdx.x] = a; sQ[threadIdx.x] = q;
    __syncthreads();
    for (int step = 32; step > 0; step >>= 1) {
        if (threadIdx.x < step) {
            ss[threadIdx.x] += ss[threadIdx.x + step];
            sQ[threadIdx.x] += sQ[threadIdx.x + step];
        }
        __syncthreads();
    }
    if (threadIdx.x == 0) {
        float mean = ss[0] * invN;
        float var  = sQ[0] * invN - mean * mean;
        float sc   = g[c] * rsqrtf(var + 1e-5f);
        scale[c] = sc;
        shift[c] = be[c] - mean * sc;
    }
}

// ---------------------------------------------------------------------------
// Deformable resample on RAW activations, applying BN (sc,sh per channel) on
// the interpolated value (bilinear interp commutes with affine maps).
// Offsets consumed exactly as torch's flat view:
//   idx = (b*C + c)*HW + p  ->  di = off[2*idx], dj = off[2*idx + 1]
// ---------------------------------------------------------------------------
__global__ __launch_bounds__(256)
void deform_resample_kernel(const float* __restrict__ x, const float* __restrict__ off,
                            const float* __restrict__ sc, const float* __restrict__ sh,
                            float* __restrict__ out, int H, int W, int C, long total)
{
    const int HW = H * W;
    long stride = (long)gridDim.x * blockDim.x;
    for (long idx = (long)blockIdx.x * blockDim.x + threadIdx.x; idx < total; idx += stride) {
        long bc = idx / HW;
        int  p  = (int)(idx - bc * HW);
        int  c  = (int)(bc % C);
        int  i  = p / W;
        int  j  = p - i * W;
        float di = off[2 * idx];
        float dj = off[2 * idx + 1];
        float ci = fminf(fmaxf(di + (float)i, 0.f), (float)(H - 1));
        float cj = fminf(fmaxf(dj + (float)j, 0.f), (float)(W - 1));
        float fi0 = floorf(ci), fi1 = ceilf(ci);
        float fj0 = floorf(cj), fj1 = ceilf(cj);
        int i0 = (int)fi0, i1 = (int)fi1, j0 = (int)fj0, j1 = (int)fj1;
        const float* xb = x + bc * (long)HW;
        float v00 = xb[i0 * W + j0];
        float v10 = xb[i1 * W + j0];
        float v01 = xb[i0 * W + j1];
        float v11 = xb[i1 * W + j1];
        float ddi = ci - fi0, ddj = cj - fj0;
        float top = v00 + ddi * (v10 - v00);
        float bot = v01 + ddi * (v11 - v01);
        float v   = top + ddj * (bot - top);
        out[idx] = v * sc[c] + sh[c];
    }
}

// ---------------------------------------------------------------------------
// Head: avg pool (128, 28x28) of RAW A4, apply BN4 on pooled value, FC, softmax.
// ---------------------------------------------------------------------------
__global__ __launch_bounds__(128)
void head_kernel(const float* __restrict__ a, const float* __restrict__ wfc,
                 const float* __restrict__ bfc, const float* __restrict__ sc,
                 const float* __restrict__ sh, float* __restrict__ out)
{
    const int b = blockIdx.x;
    const int c = threadIdx.x;     // 0..127
    __shared__ float pool[128];
    __shared__ float logits[10];

    const float* p = a + ((size_t)b * 128 + c) * 784;
    float s = 0.f;
    for (int i = 0; i < 784; ++i) s += p[i];
    pool[c] = (s * (1.f / 784.f)) * sc[c] + sh[c];
    __syncthreads();

    if (c < 10) {
        float l = bfc[c];
        const float* w = wfc + c * 128;
        for (int k = 0; k < 128; ++k) l = fmaf(w[k], pool[k], l);
        logits[c] = l;
    }
    __syncthreads();

    if (c == 0) {
        float mx = logits[0];
        for (int r = 1; r < 10; ++r) mx = fmaxf(mx, logits[r]);
        float sum = 0.f;
        float e[10];
        for (int r = 0; r < 10; ++r) { e[r] = expf(logits[r] - mx); sum += e[r]; }
        float inv = 1.f / sum;
        for (int r = 0; r < 10; ++r) out[b * 10 + r] = e[r] * inv;
    }
}

// ---------------------------------------------------------------------------
// Host orchestration
// ---------------------------------------------------------------------------
static void run_conv(int stride, const float* in, const float* w, const float* bias,
                     const float* bnsc, const float* bnsh, float* out,
                     int Cin, int Cout, int Hin, int Win, int doRelu)
{
    int Hout = (Hin - 1) / stride + 1;
    int Wout = (Win - 1) / stride + 1;
    int tilesX = (Wout + 31) / 32;
    dim3 block(256);
    if (stride == 1) {
        int tilesY = (Hout + 15) / 16;
        dim3 grid(tilesX * tilesY, Cout / 32, B_);
        conv3x3_f2_kernel<1, 8, 16><<<grid, block>>>(in, w, bias, bnsc, bnsh, out,
            Cin, Cout, Hin, Win, Hout, Wout, tilesX, doRelu);
    } else {
        int tilesY = (Hout + 7) / 8;
        dim3 grid(tilesX * tilesY, Cout / 32, B_);
        conv3x3_f2_kernel<2, 4, 8><<<grid, block>>>(in, w, bias, bnsc, bnsh, out,
            Cin, Cout, Hin, Win, Hout, Wout, tilesX, doRelu);
    }
}

static void run_bn_stats(const float* act, int C, int HW, const float* g, const float* be,
                         float* psum, float* psq, float* scale, float* shift)
{
    const int S = 64;
    dim3 gp(C, S);
    bn_partial_kernel<<<gp, 256>>>(act, psum, psq, C, HW, S);
    bn_finalize_kernel<<<C, 64>>>(psum, psq, g, be, scale, shift, S, 1.f / ((float)B_ * HW));
}

extern "C" void kernel_launch(void* const* d_in, const int* in_sizes, int n_in,
                              void* d_out, int out_size)
{
    (void)in_sizes; (void)n_in; (void)out_size;
    const float* x      = (const float*)d_in[0];
    const float* w11    = (const float*)d_in[1];
    const float* b11    = (const float*)d_in[2];
    const float* g11    = (const float*)d_in[3];
    const float* be11   = (const float*)d_in[4];
    const float* woff12 = (const float*)d_in[5];
    const float* w12    = (const float*)d_in[6];
    const float* b12    = (const float*)d_in[7];
    const float* g12    = (const float*)d_in[8];
    const float* be12   = (const float*)d_in[9];
    const float* woff21 = (const float*)d_in[10];
    const float* w21    = (const float*)d_in[11];
    const float* b21    = (const float*)d_in[12];
    const float* g21    = (const float*)d_in[13];
    const float* be21   = (const float*)d_in[14];
    const float* woff22 = (const float*)d_in[15];
    const float* w22    = (const float*)d_in[16];
    const float* b22    = (const float*)d_in[17];
    const float* g22    = (const float*)d_in[18];
    const float* be22   = (const float*)d_in[19];
    const float* wfc    = (const float*)d_in[20];
    const float* bfc    = (const float*)d_in[21];
    float* out = (float*)d_out;

    float* base = nullptr;
    cudaGetSymbolAddress((void**)&base, g_buf);

    float* A1   = base + OFF_A1;
    float* OFF1 = base + OFF_OFF1;
    float* D1   = base + OFF_D1;
    float* A2   = base + OFF_A2;
    float* OFF2 = base + OFF_OFF2;
    float* D2   = base + OFF_D2;
    float* A3   = base + OFF_A3;
    float* OFF3 = base + OFF_OFF3;
    float* D3   = base + OFF_D3;
    float* A4   = base + OFF_A4;
    float* PSUM = base + OFF_PSUM;
    float* PSQ  = base + OFF_PSQ;
    float* SC1  = base + OFF_SC1;  float* SH1 = base + OFF_SH1;
    float* SC2  = base + OFF_SC2;  float* SH2 = base + OFF_SH2;
    float* SC3  = base + OFF_SC3;  float* SH3 = base + OFF_SH3;
    float* SC4  = base + OFF_SC4;  float* SH4 = base + OFF_SH4;

    // ---- stage 1 @112x112: A1 = relu(conv(x)); BN1 stats only ----
    run_conv(1, x, w11, b11, nullptr, nullptr, A1, 1, 32, 112, 112, /*relu=*/1);
    run_bn_stats(A1, 32, 112 * 112, g11, be11, PSUM, PSQ, SC1, SH1);

    // offset conv consumes BN1(A1): affine applied during smem staging
    run_conv(1, A1, woff12, nullptr, SC1, SH1, OFF1, 32, 64, 112, 112, 0);
    {
        long total = (long)B_ * 32 * 112 * 112;
        deform_resample_kernel<<<4096, 256>>>(A1, OFF1, SC1, SH1, D1, 112, 112, 32, total);
    }

    // ---- stage 2: s2 conv -> 56x56 ----
    run_conv(2, D1, w12, b12, nullptr, nullptr, A2, 32, 64, 112, 112, 1);
    run_bn_stats(A2, 64, 56 * 56, g12, be12, PSUM, PSQ, SC2, SH2);

    run_conv(1, A2, woff21, nullptr, SC2, SH2, OFF2, 64, 128, 56, 56, 0);
    {
        long total = (long)B_ * 64 * 56 * 56;
        deform_resample_kernel<<<4096, 256>>>(A2, OFF2, SC2, SH2, D2, 56, 56, 64, total);
    }

    // ---- stage 3 @56x56 ----
    run_conv(1, D2, w21, b21, nullptr, nullptr, A3, 64, 128, 56, 56, 1);
    run_bn_stats(A3, 128, 56 * 56, g21, be21, PSUM, PSQ, SC3, SH3);

    run_conv(1, A3, woff22, nullptr, SC3, SH3, OFF3, 128, 256, 56, 56, 0);
    {
        long total = (long)B_ * 128 * 56 * 56;
        deform_resample_kernel<<<4096, 256>>>(A3, OFF3, SC3, SH3, D3, 56, 56, 128, total);
    }

    // ---- stage 4: s2 conv -> 28x28 ----
    run_conv(2, D3, w22, b22, nullptr, nullptr, A4, 128, 128, 56, 56, 1);
    run_bn_stats(A4, 128, 28 * 28, g22, be22, PSUM, PSQ, SC4, SH4);

    // ---- head (applies BN4 on pooled values) ----
    head_kernel<<<B_, 128>>>(A4, wfc, bfc, SC4, SH4, out);
}

// round 13
// speedup vs baseline: 1.0246x; 1.0246x over previous
#include <cuda_runtime.h>
#include <math.h>
#include <stdint.h>

// ---------------------------------------------------------------------------
// Shapes (fixed for this problem)
//   x:    (64, 1, 112, 112)
//   s1: conv 1->32 s1  @112 ; BN ; deform(32) @112
//   s2: conv 32->64 s2 @112->56 ; BN ; deform(64) @56
//   s3: conv 64->128 s1 @56 ; BN ; deform(128) @56
//   s4: conv 128->128 s2 @56->28 ; BNstats ; pool(+BN4 fold)+fc+softmax
// Stride-1 convs: cp.async-staged, 8-cin chunks, 2 barriers / 8 cins, FFMA2.
// Stride-2 convs: proven register-prefetch FFMA2 kernel.
// ---------------------------------------------------------------------------

#define B_ 64

// ---- scratch buffer (single __device__ global; offsets in floats) ----------
constexpr size_t SZ_A1   = (size_t)B_ * 32 * 112 * 112;
constexpr size_t SZ_OFF1 = (size_t)B_ * 64 * 112 * 112;
constexpr size_t SZ_D1   = SZ_A1;
constexpr size_t SZ_A2   = (size_t)B_ * 64 * 56 * 56;
constexpr size_t SZ_OFF2 = (size_t)B_ * 128 * 56 * 56;
constexpr size_t SZ_D2   = SZ_A2;
constexpr size_t SZ_A3   = (size_t)B_ * 128 * 56 * 56;
constexpr size_t SZ_OFF3 = (size_t)B_ * 256 * 56 * 56;
constexpr size_t SZ_D3   = SZ_A3;
constexpr size_t SZ_A4   = (size_t)B_ * 128 * 28 * 28;
constexpr size_t SZ_PART = (size_t)128 * 64;
constexpr size_t SZ_SS   = 128;

constexpr size_t OFF_A1   = 0;
constexpr size_t OFF_OFF1 = OFF_A1   + SZ_A1;
constexpr size_t OFF_D1   = OFF_OFF1 + SZ_OFF1;
constexpr size_t OFF_A2   = OFF_D1   + SZ_D1;
constexpr size_t OFF_OFF2 = OFF_A2   + SZ_A2;
constexpr size_t OFF_D2   = OFF_OFF2 + SZ_OFF2;
constexpr size_t OFF_A3   = OFF_D2   + SZ_D2;
constexpr size_t OFF_OFF3 = OFF_A3   + SZ_A3;
constexpr size_t OFF_D3   = OFF_OFF3 + SZ_OFF3;
constexpr size_t OFF_A4   = OFF_D3   + SZ_D3;
constexpr size_t OFF_PSUM = OFF_A4   + SZ_A4;
constexpr size_t OFF_PSQ  = OFF_PSUM + SZ_PART;
constexpr size_t OFF_SC   = OFF_PSQ  + SZ_PART;
constexpr size_t OFF_SH   = OFF_SC   + SZ_SS;
constexpr size_t TOTAL_F  = OFF_SH   + SZ_SS;

__device__ float g_buf[TOTAL_F];

// ---- packed fp32x2 helpers (Blackwell FFMA2 path; bit-exact fp32) ----------
typedef unsigned long long u64t;

__device__ __forceinline__ u64t pack2(float lo, float hi) {
    u64t d;
    asm("mov.b64 %0, {%1, %2};" : "=l"(d) : "f"(lo), "f"(hi));
    return d;
}
__device__ __forceinline__ void unpack2(u64t v, float& lo, float& hi) {
    asm("mov.b64 {%0, %1}, %2;" : "=f"(lo), "=f"(hi) : "l"(v));
}
__device__ __forceinline__ u64t fma2(u64t a, u64t b, u64t c) {
    u64t d;
    asm("fma.rn.f32x2 %0, %1, %2, %3;" : "=l"(d) : "l"(a), "l"(b), "l"(c));
    return d;
}

// ---------------------------------------------------------------------------
// Stride-1 3x3 conv, pad=1: cp.async staging + FFMA2.
// 256 threads; output tile 32(x) x 16(y) x 32 co; thread = 8 px x 8 co.
// Input staged 8 channels per chunk into dynamic smem (double-buffered);
// 2 __syncthreads per 8 cins. Weights staged per 32-cin group.
// ---------------------------------------------------------------------------
constexpr int C1_TOX = 32, C1_TOY = 16, C1_KO = 32, C1_CH = 32, C1_CHS = 8;
constexpr int C1_PX  = 8;
constexpr int C1_IW  = C1_TOX + 2;            // 34
constexpr int C1_IWP = C1_IW + 1;             // 35
constexpr int C1_IH  = C1_TOY + 2;            // 18
constexpr int C1_NPIX  = C1_IH * C1_IWP;      // 630
constexpr int C1_NSLOT = (C1_NPIX + 255) / 256;  // 3
constexpr int C1_NC  = C1_PX + 2;             // 10
constexpr int C1_WFLOATS  = C1_CH * 9 * C1_KO;            // 9216
constexpr int C1_INFLOATS = 2 * C1_CHS * C1_NPIX;         // 10080
constexpr int C1_SMEMB = (C1_WFLOATS + C1_INFLOATS) * 4;  // 77184 bytes

__global__ __launch_bounds__(256, 2)
void conv3x3_cp_kernel(const float* __restrict__ in, const float* __restrict__ wgt,
                       const float* __restrict__ bias, float* __restrict__ out,
                       int Cin, int Cout, int Hin, int Win, int Hout, int Wout,
                       int tilesX, int doRelu)
{
    extern __shared__ float smem[];
    float* s_w  = smem;                    // [CH*9*KO]
    float* s_in = smem + C1_WFLOATS;       // [2][CHS][NPIX]

    const int b    = blockIdx.z;
    const int co0  = blockIdx.y * C1_KO;
    const int tile = blockIdx.x;
    const int oy0  = (tile / tilesX) * C1_TOY;
    const int ox0  = (tile % tilesX) * C1_TOX;
    const int tid  = threadIdx.x;
    const int cog  = tid >> 6;                 // 0..3 -> 8 co's
    const int rem  = tid & 63;
    const int ty   = rem >> 2;                 // 0..15
    const int txg  = rem & 3;                  // pixel col group of 8

    const int iy0 = oy0 - 1;
    const int ix0 = ox0 - 1;
    const int rbase = ty;
    const int cbase = txg * C1_PX;
    const int HinWin = Hin * Win;

    // per-thread staging slots (ci-invariant)
    int  soff[C1_NSLOT];
    bool sval[C1_NSLOT];
    bool sput[C1_NSLOT];
    #pragma unroll
    for (int s = 0; s < C1_NSLOT; ++s) {
        int idx = tid + s * 256;
        int r = idx / C1_IWP, c = idx - r * C1_IWP;
        int iy = iy0 + r, ix = ix0 + c;
        sput[s] = (idx < C1_NPIX);
        sval[s] = sput[s] && (c < C1_IW) && iy >= 0 && iy < Hin && ix >= 0 && ix < Win;
        soff[s] = iy * Win + ix;
    }

    const float* inB = in + (size_t)b * Cin * HinWin;
    const unsigned s_in_u32 = (unsigned)__cvta_generic_to_shared(s_in);

    // issue cp.async for an 8-channel chunk into buffer (c8 & 1); always commits
    auto issue_chunk = [&](int c8) {
        int cb = c8 * C1_CHS;
        unsigned bufbase = s_in_u32 + (unsigned)((c8 & 1) * C1_CHS * C1_NPIX) * 4u;
        #pragma unroll
        for (int ch = 0; ch < C1_CHS; ++ch) {
            int ci = cb + ch;
            bool chok = (ci < Cin);
            const float* inC = inB + (size_t)(chok ? ci : 0) * HinWin;
            #pragma unroll
            for (int s = 0; s < C1_NSLOT; ++s) {
                if (!sput[s]) continue;
                unsigned dst = bufbase + (unsigned)(ch * C1_NPIX + tid + s * 256) * 4u;
                bool ok = chok && sval[s];
                const float* src = ok ? (inC + soff[s]) : inB;   // valid addr always
                int sz = ok ? 4 : 0;
                asm volatile("cp.async.ca.shared.global [%0], [%1], 4, %2;"
                             :: "r"(dst), "l"(__cvta_generic_to_global(src)), "r"(sz));
            }
        }
        asm volatile("cp.async.commit_group;" ::: "memory");
    };

    auto stage_w = [&](int cb) {
        const int ce  = (cb + C1_CH < Cin) ? cb + C1_CH : Cin;
        const int cnt = ce - cb;
        for (int i = tid; i < cnt * 9 * C1_KO; i += 256) {
            int col = i & (C1_KO - 1);
            int t   = i >> 5;
            int k   = t % 9;
            int cl  = t / 9;
            s_w[i] = wgt[((size_t)(co0 + col) * Cin + (cb + cl)) * 9 + k];
        }
    };

    u64t acc[4][C1_PX];
    #pragma unroll
    for (int mp = 0; mp < 4; ++mp)
        #pragma unroll
        for (int p = 0; p < C1_PX; ++p) acc[mp][p] = 0ull;

    const int nch8 = (Cin + C1_CHS - 1) / C1_CHS;

    // prologue: chunks 0 and 1 in flight
    issue_chunk(0);
    issue_chunk(1);

    for (int c8 = 0; c8 < nch8; ++c8) {
        const int cb = c8 * C1_CHS;
        if ((cb & (C1_CH - 1)) == 0) stage_w(cb);    // prev compute done (trailing bar)

        asm volatile("cp.async.wait_group 1;" ::: "memory");
        __syncthreads();                              // staging + weights visible

        const int cend = (cb + C1_CHS < Cin) ? C1_CHS : (Cin - cb);
        const float* bufp = s_in + (c8 & 1) * (C1_CHS * C1_NPIX);
        for (int j = 0; j < cend; ++j) {
            const int cl = (cb + j) & (C1_CH - 1);
            const float* xp = bufp + j * C1_NPIX + rbase * C1_IWP + cbase;
            const float* wb = s_w + (cl * 9) * C1_KO + cog * 8;
            #pragma unroll
            for (int kr = 0; kr < 3; ++kr) {
                u64t xs[C1_NC];
                #pragma unroll
                for (int c = 0; c < C1_NC; ++c) {
                    float v = xp[kr * C1_IWP + c];
                    xs[c] = pack2(v, v);
                }
                #pragma unroll
                for (int kc = 0; kc < 3; ++kc) {
                    const float* wk = wb + (kr * 3 + kc) * C1_KO;
                    u64t w0 = *(const u64t*)(wk + 0);
                    u64t w1 = *(const u64t*)(wk + 2);
                    u64t w2 = *(const u64t*)(wk + 4);
                    u64t w3 = *(const u64t*)(wk + 6);
                    #pragma unroll
                    for (int p = 0; p < C1_PX; ++p) {
                        u64t x = xs[p + kc];
                        acc[0][p] = fma2(w0, x, acc[0][p]);
                        acc[1][p] = fma2(w1, x, acc[1][p]);
                        acc[2][p] = fma2(w2, x, acc[2][p]);
                        acc[3][p] = fma2(w3, x, acc[3][p]);
                    }
                }
            }
        }

        __syncthreads();                              // buffer free for reuse
        issue_chunk(c8 + 2);
    }

    // epilogue
    const int oy = oy0 + ty;
    if (oy < Hout) {
        #pragma unroll
        for (int mp = 0; mp < 4; ++mp) {
            int coL = co0 + cog * 8 + mp * 2;
            float bL = bias ? bias[coL] : 0.f;
            float bH = bias ? bias[coL + 1] : 0.f;
            float* oL = out + ((size_t)b * Cout + coL) * (size_t)Hout * Wout + (size_t)oy * Wout;
            float* oH = oL + (size_t)Hout * Wout;
            #pragma unroll
            for (int p = 0; p < C1_PX; ++p) {
                int ox = ox0 + txg * C1_PX + p;
                if (ox < Wout) {
                    float lo, hi;
                    unpack2(acc[mp][p], lo, hi);
                    lo += bL; hi += bH;
                    if (doRelu) { lo = fmaxf(lo, 0.f); hi = fmaxf(hi, 0.f); }
                    oL[ox] = lo;
                    oH[ox] = hi;
                }
            }
        }
    }
}

// ---------------------------------------------------------------------------
// Stride-2 3x3 conv (proven R7-style register-prefetch FFMA2 kernel).
// 256 threads; tile 32(x) x 8(y) x 32 co; thread = 4 px x 8 co.
// ---------------------------------------------------------------------------
__global__ __launch_bounds__(256)
void conv3x3_s2_kernel(const float* __restrict__ in, const float* __restrict__ wgt,
                       const float* __restrict__ bias, float* __restrict__ out,
                       int Cin, int Cout, int Hin, int Win, int Hout, int Wout,
                       int tilesX, int doRelu)
{
    constexpr int STRIDE = 2, PX = 4, TOY = 8;
    constexpr int TOX = 32, KO = 32, CH = 32;
    constexpr int TXG = TOX / PX;                 // 8
    constexpr int IW  = (TOX - 1) * STRIDE + 3;   // 65
    constexpr int IWP = IW + 1;                   // 66
    constexpr int IH  = (TOY - 1) * STRIDE + 3;   // 17
    constexpr int NPIX  = IH * IWP;               // 1122
    constexpr int NSLOT = (NPIX + 255) / 256;     // 5
    constexpr int NC  = (PX - 1) * STRIDE + 3;    // 9

    __shared__ float s_in[2][NPIX];
    __shared__ float s_w[CH * 9 * KO];

    const int b    = blockIdx.z;
    const int co0  = blockIdx.y * KO;
    const int tile = blockIdx.x;
    const int oy0  = (tile / tilesX) * TOY;
    const int ox0  = (tile % tilesX) * TOX;
    const int tid  = threadIdx.x;
    const int cog  = tid >> 6;
    const int rem  = tid & 63;
    const int ty   = rem / TXG;
    const int txg  = rem % TXG;

    const int iy0 = oy0 * STRIDE - 1;
    const int ix0 = ox0 * STRIDE - 1;
    const int rbase = ty * STRIDE;
    const int cbase = txg * PX * STRIDE;
    const int HinWin = Hin * Win;

    int  soff[NSLOT];
    bool sval[NSLOT];
    bool sput[NSLOT];
    #pragma unroll
    for (int s = 0; s < NSLOT; ++s) {
        int idx = tid + s * 256;
        int r = idx / IWP, c = idx - r * IWP;
        int iy = iy0 + r, ix = ix0 + c;
        sput[s] = (idx < NPIX);
        sval[s] = sput[s] && (c < IW) && iy >= 0 && iy < Hin && ix >= 0 && ix < Win;
        soff[s] = iy * Win + ix;
    }

    const float* inB = in + (size_t)b * Cin * HinWin;
    float rg[NSLOT];

    auto prefetch = [&](int ci) {
        const float* inC = inB + (size_t)ci * HinWin;
        #pragma unroll
        for (int s = 0; s < NSLOT; ++s)
            rg[s] = sval[s] ? __ldg(inC + soff[s]) : 0.f;
    };
    auto put = [&](int bufi) {
        #pragma unroll
        for (int s = 0; s < NSLOT; ++s)
            if (sput[s]) s_in[bufi][tid + s * 256] = rg[s];
    };
    auto stage_w = [&](int cb) {
        const int ce  = (cb + CH < Cin) ? cb + CH : Cin;
        const int cnt = ce - cb;
        for (int i = tid; i < cnt * 9 * KO; i += 256) {
            int col = i & (KO - 1);
            int t   = i >> 5;
            int k   = t % 9;
            int cl  = t / 9;
            s_w[i] = wgt[((size_t)(co0 + col) * Cin + (cb + cl)) * 9 + k];
        }
    };

    u64t acc[4][PX];
    #pragma unroll
    for (int mp = 0; mp < 4; ++mp)
        #pragma unroll
        for (int p = 0; p < PX; ++p) acc[mp][p] = 0ull;

    prefetch(0);
    put(0);
    if (Cin > 1) prefetch(1);
    stage_w(0);
    __syncthreads();

    for (int ci = 0; ci < Cin; ++ci) {
        if (ci + 1 < Cin) put((ci + 1) & 1);
        if (ci + 2 < Cin) prefetch(ci + 2);

        {
            const int cl = ci & (CH - 1);
            const float* xp = s_in[ci & 1] + rbase * IWP + cbase;
            const float* wb = s_w + (cl * 9) * KO + cog * 8;
            #pragma unroll
            for (int kr = 0; kr < 3; ++kr) {
                u64t xs[NC];
                #pragma unroll
                for (int c = 0; c < NC; ++c) {
                    float v = xp[kr * IWP + c];
                    xs[c] = pack2(v, v);
                }
                #pragma unroll
                for (int kc = 0; kc < 3; ++kc) {
                    const float* wk = wb + (kr * 3 + kc) * KO;
                    u64t w0 = *(const u64t*)(wk + 0);
                    u64t w1 = *(const u64t*)(wk + 2);
                    u64t w2 = *(const u64t*)(wk + 4);
                    u64t w3 = *(const u64t*)(wk + 6);
                    #pragma unroll
                    for (int p = 0; p < PX; ++p) {
                        u64t x = xs[p * STRIDE + kc];
                        acc[0][p] = fma2(w0, x, acc[0][p]);
                        acc[1][p] = fma2(w1, x, acc[1][p]);
                        acc[2][p] = fma2(w2, x, acc[2][p]);
                        acc[3][p] = fma2(w3, x, acc[3][p]);
                    }
                }
            }
        }

        if ((ci + 1) < Cin && ((ci + 1) & (CH - 1)) == 0) {
            __syncthreads();
            stage_w(ci + 1);
        }
        __syncthreads();
    }

    const int oy = oy0 + ty;
    if (oy < Hout) {
        #pragma unroll
        for (int mp = 0; mp < 4; ++mp) {
            int coL = co0 + cog * 8 + mp * 2;
            float bL = bias ? bias[coL] : 0.f;
            float bH = bias ? bias[coL + 1] : 0.f;
            float* oL = out + ((size_t)b * Cout + coL) * (size_t)Hout * Wout + (size_t)oy * Wout;
            float* oH = oL + (size_t)Hout * Wout;
            #pragma unroll
            for (int p = 0; p < PX; ++p) {
                int ox = ox0 + txg * PX + p;
                if (ox < Wout) {
                    float lo, hi;
                    unpack2(acc[mp][p], lo, hi);
                    lo += bL; hi += bH;
                    if (doRelu) { lo = fmaxf(lo, 0.f); hi = fmaxf(hi, 0.f); }
                    oL[ox] = lo;
                    oH[ox] = hi;
                }
            }
        }
    }
}

// ---------------------------------------------------------------------------
// BN: deterministic two-stage reduction over (N, H, W) per channel.
// ---------------------------------------------------------------------------
__global__ __launch_bounds__(256)
void bn_partial_kernel(const float* __restrict__ x, float* __restrict__ psum,
                       float* __restrict__ psq, int C, int HW, int S)
{
    const int c = blockIdx.x;
    const int s = blockIdx.y;
    const long n = (long)B_ * HW;
    const long chunk = (n + S - 1) / S;
    const long lo = (long)s * chunk;
    const long hi = (lo + chunk < n) ? lo + chunk : n;

    float sum = 0.f, sq = 0.f;
    for (long i = lo + threadIdx.x; i < hi; i += 256) {
        long b = i / HW;
        int  p = (int)(i - b * HW);
        float v = x[(b * C + c) * (long)HW + p];
        sum += v;
        sq  += v * v;
    }
    __shared__ float ss[256], sQ[256];
    ss[threadIdx.x] = sum;
    sQ[threadIdx.x] = sq;
    __syncthreads();
    for (int step = 128; step > 0; step >>= 1) {
        if (threadIdx.x < step) {
            ss[threadIdx.x] += ss[threadIdx.x + step];
            sQ[threadIdx.x] += sQ[threadIdx.x + step];
        }
        __syncthreads();
    }
    if (threadIdx.x == 0) {
        psum[c * S + s] = ss[0];
        psq [c * S + s] = sQ[0];
    }
}

__global__ void bn_finalize_kernel(const float* __restrict__ psum, const float* __restrict__ psq,
                                   const float* __restrict__ g, const float* __restrict__ be,
                                   float* __restrict__ scale, float* __restrict__ shift,
                                   int S, float invN)
{
    const int c = blockIdx.x;
    __shared__ float ss[64], sQ[64];
    float a = 0.f, q = 0.f;
    if (threadIdx.x < S) { a = psum[c * S + threadIdx.x]; q = psq[c * S + threadIdx.x]; }
    ss[threadIdx.x] = a; sQ[threadIdx.x] = q;
    __syncthreads();
    for (int step = 32; step > 0; step >>= 1) {
        if (threadIdx.x < step) {
            ss[threadIdx.x] += ss[threadIdx.x + step];
            sQ[threadIdx.x] += sQ[threadIdx.x + step];
        }
        __syncthreads();
    }
    if (threadIdx.x == 0) {
        float mean = ss[0] * invN;
        float var  = sQ[0] * invN - mean * mean;
        float sc   = g[c] * rsqrtf(var + 1e-5f);
        scale[c] = sc;
        shift[c] = be[c] - mean * sc;
    }
}

__global__ __launch_bounds__(256)
void bn_apply_kernel(float* __restrict__ x, const float* __restrict__ scale,
                     const float* __restrict__ shift, int C, int HW, long total)
{
    long stride = (long)gridDim.x * blockDim.x;
    for (long i = (long)blockIdx.x * blockDim.x + threadIdx.x; i < total; i += stride) {
        int c = (int)((i / HW) % C);
        x[i] = x[i] * scale[c] + shift[c];
    }
}

// ---------------------------------------------------------------------------
// Deformable resample (input already BN'd). Offsets consumed as torch flat view:
//   idx = (b*C + c)*HW + p  ->  di = off[2*idx], dj = off[2*idx + 1]
// ---------------------------------------------------------------------------
__global__ __launch_bounds__(256)
void deform_resample_kernel(const float* __restrict__ x, const float* __restrict__ off,
                            float* __restrict__ out, int H, int W, long total)
{
    const int HW = H * W;
    long stride = (long)gridDim.x * blockDim.x;
    for (long idx = (long)blockIdx.x * blockDim.x + threadIdx.x; idx < total; idx += stride) {
        long bc = idx / HW;
        int  p  = (int)(idx - bc * HW);
        int  i  = p / W;
        int  j  = p - i * W;
        float di = off[2 * idx];
        float dj = off[2 * idx + 1];
        float ci = fminf(fmaxf(di + (float)i, 0.f), (float)(H - 1));
        float cj = fminf(fmaxf(dj + (float)j, 0.f), (float)(W - 1));
        float fi0 = floorf(ci), fi1 = ceilf(ci);
        float fj0 = floorf(cj), fj1 = ceilf(cj);
        int i0 = (int)fi0, i1 = (int)fi1, j0 = (int)fj0, j1 = (int)fj1;
        const float* xb = x + bc * (long)HW;
        float v00 = xb[i0 * W + j0];
        float v10 = xb[i1 * W + j0];
        float v01 = xb[i0 * W + j1];
        float v11 = xb[i1 * W + j1];
        float ddi = ci - fi0, ddj = cj - fj0;
        float top = v00 + ddi * (v10 - v00);
        float bot = v01 + ddi * (v11 - v01);
        out[idx] = top + ddj * (bot - top);
    }
}

// ---------------------------------------------------------------------------
// Head: avg pool (128, 28x28) of RAW A4, apply BN4 on pooled value, FC, softmax.
// ---------------------------------------------------------------------------
__global__ __launch_bounds__(128)
void head_kernel(const float* __restrict__ a, const float* __restrict__ wfc,
                 const float* __restrict__ bfc, const float* __restrict__ sc,
                 const float* __restrict__ sh, float* __restrict__ out)
{
    const int b = blockIdx.x;
    const int c = threadIdx.x;     // 0..127
    __shared__ float pool[128];
    __shared__ float logits[10];

    const float* p = a + ((size_t)b * 128 + c) * 784;
    float s = 0.f;
    for (int i = 0; i < 784; ++i) s += p[i];
    pool[c] = (s * (1.f / 784.f)) * sc[c] + sh[c];
    __syncthreads();

    if (c < 10) {
        float l = bfc[c];
        const float* w = wfc + c * 128;
        for (int k = 0; k < 128; ++k) l = fmaf(w[k], pool[k], l);
        logits[c] = l;
    }
    __syncthreads();

    if (c == 0) {
        float mx = logits[0];
        for (int r = 1; r < 10; ++r) mx = fmaxf(mx, logits[r]);
        float sum = 0.f;
        float e[10];
        for (int r = 0; r < 10; ++r) { e[r] = expf(logits[r] - mx); sum += e[r]; }
        float inv = 1.f / sum;
        for (int r = 0; r < 10; ++r) out[b * 10 + r] = e[r] * inv;
    }
}

// ---------------------------------------------------------------------------
// Host orchestration
// ---------------------------------------------------------------------------
static void run_conv(int stride, const float* in, const float* w, const float* bias,
                     float* out, int Cin, int Cout, int Hin, int Win, int doRelu)
{
    int Hout = (Hin - 1) / stride + 1;
    int Wout = (Win - 1) / stride + 1;
    int tilesX = (Wout + 31) / 32;
    dim3 block(256);
    if (stride == 1) {
        static bool attr_set = false;
        if (!attr_set) {
            cudaFuncSetAttribute(conv3x3_cp_kernel,
                                 cudaFuncAttributeMaxDynamicSharedMemorySize, C1_SMEMB);
            attr_set = true;
        }
        int tilesY = (Hout + C1_TOY - 1) / C1_TOY;
        dim3 grid(tilesX * tilesY, Cout / 32, B_);
        conv3x3_cp_kernel<<<grid, block, C1_SMEMB>>>(in, w, bias, out,
            Cin, Cout, Hin, Win, Hout, Wout, tilesX, doRelu);
    } else {
        int tilesY = (Hout + 7) / 8;
        dim3 grid(tilesX * tilesY, Cout / 32, B_);
        conv3x3_s2_kernel<<<grid, block>>>(in, w, bias, out,
            Cin, Cout, Hin, Win, Hout, Wout, tilesX, doRelu);
    }
}

static void run_bn(float* act, int C, int HW, const float* g, const float* be,
                   float* psum, float* psq, float* scale, float* shift, bool apply)
{
    const int S = 64;
    dim3 gp(C, S);
    bn_partial_kernel<<<gp, 256>>>(act, psum, psq, C, HW, S);
    bn_finalize_kernel<<<C, 64>>>(psum, psq, g, be, scale, shift, S, 1.f / ((float)B_ * HW));
    if (apply) {
        long total = (long)B_ * C * HW;
        bn_apply_kernel<<<2048, 256>>>(act, scale, shift, C, HW, total);
    }
}

extern "C" void kernel_launch(void* const* d_in, const int* in_sizes, int n_in,
                              void* d_out, int out_size)
{
    (void)in_sizes; (void)n_in; (void)out_size;
    const float* x      = (const float*)d_in[0];
    const float* w11    = (const float*)d_in[1];
    const float* b11    = (const float*)d_in[2];
    const float* g11    = (const float*)d_in[3];
    const float* be11   = (const float*)d_in[4];
    const float* woff12 = (const float*)d_in[5];
    const float* w12    = (const float*)d_in[6];
    const float* b12    = (const float*)d_in[7];
    const float* g12    = (const float*)d_in[8];
    const float* be12   = (const float*)d_in[9];
    const float* woff21 = (const float*)d_in[10];
    const float* w21    = (const float*)d_in[11];
    const float* b21    = (const float*)d_in[12];
    const float* g21    = (const float*)d_in[13];
    const float* be21   = (const float*)d_in[14];
    const float* woff22 = (const float*)d_in[15];
    const float* w22    = (const float*)d_in[16];
    const float* b22    = (const float*)d_in[17];
    const float* g22    = (const float*)d_in[18];
    const float* be22   = (const float*)d_in[19];
    const float* wfc    = (const float*)d_in[20];
    const float* bfc    = (const float*)d_in[21];
    float* out = (float*)d_out;

    float* base = nullptr;
    cudaGetSymbolAddress((void**)&base, g_buf);

    float* A1   = base + OFF_A1;
    float* OFF1 = base + OFF_OFF1;
    float* D1   = base + OFF_D1;
    float* A2   = base + OFF_A2;
    float* OFF2 = base + OFF_OFF2;
    float* D2   = base + OFF_D2;
    float* A3   = base + OFF_A3;
    float* OFF3 = base + OFF_OFF3;
    float* D3   = base + OFF_D3;
    float* A4   = base + OFF_A4;
    float* PSUM = base + OFF_PSUM;
    float* PSQ  = base + OFF_PSQ;
    float* SC   = base + OFF_SC;
    float* SH   = base + OFF_SH;

    // ---- stage 1 @112x112 ----
    run_conv(1, x, w11, b11, A1, 1, 32, 112, 112, /*relu=*/1);
    run_bn(A1, 32, 112 * 112, g11, be11, PSUM, PSQ, SC, SH, true);

    run_conv(1, A1, woff12, nullptr, OFF1, 32, 64, 112, 112, 0);
    {
        long total = (long)B_ * 32 * 112 * 112;
        deform_resample_kernel<<<4096, 256>>>(A1, OFF1, D1, 112, 112, total);
    }

    // ---- stage 2: s2 conv -> 56x56 ----
    run_conv(2, D1, w12, b12, A2, 32, 64, 112, 112, 1);
    run_bn(A2, 64, 56 * 56, g12, be12, PSUM, PSQ, SC, SH, true);

    run_conv(1, A2, woff21, nullptr, OFF2, 64, 128, 56, 56, 0);
    {
        long total = (long)B_ * 64 * 56 * 56;
        deform_resample_kernel<<<4096, 256>>>(A2, OFF2, D2, 56, 56, total);
    }

    // ---- stage 3 @56x56 ----
    run_conv(1, D2, w21, b21, A3, 64, 128, 56, 56, 1);
    run_bn(A3, 128, 56 * 56, g21, be21, PSUM, PSQ, SC, SH, true);

    run_conv(1, A3, woff22, nullptr, OFF3, 128, 256, 56, 56, 0);
    {
        long total = (long)B_ * 128 * 56 * 56;
        deform_resample_kernel<<<4096, 256>>>(A3, OFF3, D3, 56, 56, total);
    }

    // ---- stage 4: s2 conv -> 28x28 ----
    run_conv(2, D3, w22, b22, A4, 128, 128, 56, 56, 1);
    run_bn(A4, 128, 28 * 28, g22, be22, PSUM, PSQ, SC, SH, false);

    // ---- head (applies BN4 on pooled values) ----
    head_kernel<<<B_, 128>>>(A4, wfc, bfc, SC, SH, out);
}